// round 2
// baseline (speedup 1.0000x reference)
#include <cuda_runtime.h>

// Fixed problem shape: B=16, C=1, H=128, W=8192, NMAX=64
#define BB   16
#define HH   128
#define WW   8192
#define NMX  64
#define ROWS_PER_BLOCK 8          // grid.z = HH / ROWS_PER_BLOCK = 16
#define BIGV 0x3FFFFFFF

// ---------------------------------------------------------------------------
// Single fused kernel.
// grid = (WW/(256*4)=8, BB=16, HH/ROWS_PER_BLOCK=16), block = 256.
// Each block: recomputes the per-batch segment metadata (64-elem scan, cheap),
// then each thread handles 4 consecutive output columns across 8 rows
// (float4 stores, scalar gather loads).
// Block (0, b, 0) additionally writes xi_new to the output tail.
// ---------------------------------------------------------------------------
__global__ void __launch_bounds__(256)
pack_all_kernel(const float* __restrict__ x,
                const int*   __restrict__ xi,
                const int*   __restrict__ N,
                const float* __restrict__ sep_param,
                float* __restrict__ out,
                float* __restrict__ out_xi,   // may be null-ish if !write_xi
                int write_xi) {
    const int b = blockIdx.y;
    const int t = threadIdx.x;

    __shared__ int   s_start[NMX];
    __shared__ int   s_end[NMX];
    __shared__ int   s_src[NMX];
    __shared__ int   sh[NMX];
    __shared__ int   s_n;
    __shared__ float s_sep;

    if (t == 0) { s_n = N[b]; s_sep = sep_param[0]; }
    __syncthreads();
    const int n = s_n;

    int seg_s = 0, seg_wv = 0, seg_valid = 0;
    if (t < NMX) {
        seg_s       = xi[(b * NMX + t) * 2 + 0];
        const int e = xi[(b * NMX + t) * 2 + 1];
        const int w = max(e - seg_s, 0);
        seg_valid   = (t < n) ? 1 : 0;
        seg_wv      = seg_valid ? w : 0;
        sh[t] = seg_wv;
    }
    __syncthreads();
    #pragma unroll
    for (int off = 1; off < NMX; off <<= 1) {
        int v = (t >= off && t < NMX) ? sh[t - off] : 0;
        __syncthreads();
        if (t < NMX) sh[t] += v;
        __syncthreads();
    }
    if (t < NMX) {
        const int csum = sh[t];
        const int sn = csum - seg_wv + t;
        const int en = csum + t;
        s_start[t] = seg_valid ? sn : BIGV;   // sentinel keeps array sorted
        s_end[t]   = en;
        s_src[t]   = seg_s;
        if (write_xi && blockIdx.x == 0 && blockIdx.z == 0) {
            out_xi[(b * NMX + t) * 2 + 0] = seg_valid ? (float)sn : 0.0f;
            out_xi[(b * NMX + t) * 2 + 1] = seg_valid ? (float)en : 0.0f;
        }
    }
    __syncthreads();

    // ------------------------------------------------------------------
    // Per-column classification for 4 consecutive columns.
    // ------------------------------------------------------------------
    const int j0 = (blockIdx.x * 256 + t) * 4;
    const int nc = n;

    bool  gth[4];
    int   src[4];
    float fil[4];
    #pragma unroll
    for (int c = 0; c < 4; c++) {
        const int j = j0 + c;
        // upper_bound(start, j) - 1
        int lo = 0, hi = nc;
        while (lo < hi) {
            int mid = (lo + hi) >> 1;
            if (s_start[mid] <= j) lo = mid + 1; else hi = mid;
        }
        const int seg = lo - 1;
        gth[c] = false; src[c] = 0; fil[c] = 0.0f;
        if (seg >= 0) {
            const int s = s_start[seg];
            const int e = s_end[seg];
            if (j < e) {
                gth[c] = true;
                src[c] = min(max(s_src[seg] + (j - s), 0), WW - 1);
            } else if (j == e && seg < nc - 1) {
                fil[c] = s_sep;
            }
        }
    }

    const int h0 = blockIdx.z * ROWS_PER_BLOCK;
    const float* __restrict__ xb = x   + (size_t)b * HH * WW;
    float* __restrict__       ob = out + (size_t)b * HH * WW;

    #pragma unroll
    for (int hh = 0; hh < ROWS_PER_BLOCK; hh++) {
        const size_t row = (size_t)(h0 + hh) * WW;
        float4 v;
        v.x = gth[0] ? __ldg(xb + row + src[0]) : fil[0];
        v.y = gth[1] ? __ldg(xb + row + src[1]) : fil[1];
        v.z = gth[2] ? __ldg(xb + row + src[2]) : fil[2];
        v.w = gth[3] ? __ldg(xb + row + src[3]) : fil[3];
        *reinterpret_cast<float4*>(ob + row + j0) = v;
    }
}

// ---------------------------------------------------------------------------
extern "C" void kernel_launch(void* const* d_in, const int* in_sizes, int n_in,
                              void* d_out, int out_size) {
    const float* x   = (const float*)d_in[0];
    const int*   xi  = (const int*)  d_in[1];
    const int*   N   = (const int*)  d_in[2];
    const float* sep = (const float*)d_in[3];
    float*       out = (float*)d_out;

    const long long XN = (long long)BB * HH * WW;   // 16,777,216
    const int write_xi = ((long long)out_size > XN) ? 1 : 0;

    dim3 grid(WW / (256 * 4), BB, HH / ROWS_PER_BLOCK);
    pack_all_kernel<<<grid, 256>>>(x, xi, N, sep, out, out + XN, write_xi);
}

// round 3
// speedup vs baseline: 1.1185x; 1.1185x over previous
#include <cuda_runtime.h>

// Fixed problem shape: B=16, C=1, H=128, W=8192, NMAX=64
#define BB   16
#define HH   128
#define WW   8192
#define NMX  64
#define ROWS_PER_BLOCK 32         // grid.z = HH / 32 = 4
#define COLS_PER_THR   2
#define BIGV 0x3FFFFFFF

// ---------------------------------------------------------------------------
// Single fused kernel.
// grid = (WW/(256*2)=16, BB=16, HH/32=4) = 1024 blocks (one full wave on 148
// SMs at 8 blocks/SM max-warp occupancy), block = 256.
// Metadata (64-wide width prefix-scan) recomputed per block via warp shuffles
// (cheap: 2 warps, 5 shfl steps, 2 syncs). Each thread owns 2 consecutive
// columns x 32 rows; float2 stores, predicated scalar gather loads.
// ---------------------------------------------------------------------------
__global__ void __launch_bounds__(256)
pack_all_kernel(const float* __restrict__ x,
                const int*   __restrict__ xi,
                const int*   __restrict__ N,
                const float* __restrict__ sep_param,
                float* __restrict__ out,
                float* __restrict__ out_xi,
                int write_xi) {
    const int b = blockIdx.y;
    const int t = threadIdx.x;

    __shared__ int   s_start[NMX];
    __shared__ int   s_end[NMX];
    __shared__ int   s_src[NMX];
    __shared__ int   s_w0sum;
    __shared__ int   s_n;
    __shared__ float s_sep;

    if (t == 0) { s_n = N[b]; s_sep = sep_param[0]; }
    __syncthreads();
    const int n = s_n;

    // ---- metadata: warp-shuffle inclusive scan over 64 widths ----
    if (t < NMX) {
        const int s = xi[(b * NMX + t) * 2 + 0];
        const int e = xi[(b * NMX + t) * 2 + 1];
        const int valid = (t < n) ? 1 : 0;
        const int wv = valid ? max(e - s, 0) : 0;

        int sc = wv;
        #pragma unroll
        for (int off = 1; off < 32; off <<= 1) {
            int v = __shfl_up_sync(0xFFFFFFFFu, sc, off);
            if ((t & 31) >= off) sc += v;
        }
        if (t == 31) s_w0sum = sc;
        __syncwarp();
        // cross-warp fix handled after a block sync below
        s_end[t] = sc;       // stash partial inclusive scan temporarily
        s_src[t] = s;
        s_start[t] = valid;  // stash validity temporarily
        // keep wv in s_... ? recompute below from scan: wv needed for sn
        // store wv in shared via s_end trick: we need wv = sc - prev; simpler:
        // recompute from xi values we already have in regs after sync. We are
        // in-register here, so finish after the sync:
    }
    __syncthreads();
    if (t < NMX) {
        const int s = s_src[t];
        const int e = xi[(b * NMX + t) * 2 + 1];
        const int valid = s_start[t];
        const int wv = valid ? max(e - s, 0) : 0;
        int csum = s_end[t];
        if (t >= 32) csum += s_w0sum;
        const int sn = csum - wv + t;
        const int en = csum + t;
        s_start[t] = valid ? sn : BIGV;
        s_end[t]   = en;
        if (write_xi && blockIdx.x == 0 && blockIdx.z == 0) {
            out_xi[(b * NMX + t) * 2 + 0] = valid ? (float)sn : 0.0f;
            out_xi[(b * NMX + t) * 2 + 1] = valid ? (float)en : 0.0f;
        }
    }
    __syncthreads();

    // ---- per-column classification (2 consecutive columns) ----
    const int j0 = (blockIdx.x * 256 + t) * COLS_PER_THR;

    bool  gth[COLS_PER_THR];
    int   src[COLS_PER_THR];
    float fil[COLS_PER_THR];
    #pragma unroll
    for (int c = 0; c < COLS_PER_THR; c++) {
        const int j = j0 + c;
        int lo = 0, hi = n;
        while (lo < hi) {
            int mid = (lo + hi) >> 1;
            if (s_start[mid] <= j) lo = mid + 1; else hi = mid;
        }
        const int seg = lo - 1;
        gth[c] = false; src[c] = 0; fil[c] = 0.0f;
        if (seg >= 0) {
            const int s = s_start[seg];
            const int e = s_end[seg];
            if (j < e) {
                gth[c] = true;
                src[c] = min(max(s_src[seg] + (j - s), 0), WW - 1);
            } else if (j == e && seg < n - 1) {
                fil[c] = s_sep;
            }
        }
    }

    const int h0 = blockIdx.z * ROWS_PER_BLOCK;
    const float* __restrict__ xb = x   + (size_t)b * HH * WW + (size_t)h0 * WW;
    float* __restrict__       ob = out + (size_t)b * HH * WW + (size_t)h0 * WW;

    // 32 rows, unrolled x4: 8 independent loads batched before 4 stores.
    #pragma unroll 4
    for (int hh = 0; hh < ROWS_PER_BLOCK; hh++) {
        const size_t row = (size_t)hh * WW;
        float2 v;
        v.x = gth[0] ? __ldg(xb + row + src[0]) : fil[0];
        v.y = gth[1] ? __ldg(xb + row + src[1]) : fil[1];
        *reinterpret_cast<float2*>(ob + row + j0) = v;
    }
}

// ---------------------------------------------------------------------------
extern "C" void kernel_launch(void* const* d_in, const int* in_sizes, int n_in,
                              void* d_out, int out_size) {
    const float* x   = (const float*)d_in[0];
    const int*   xi  = (const int*)  d_in[1];
    const int*   N   = (const int*)  d_in[2];
    const float* sep = (const float*)d_in[3];
    float*       out = (float*)d_out;

    const long long XN = (long long)BB * HH * WW;   // 16,777,216
    const int write_xi = ((long long)out_size > XN) ? 1 : 0;

    dim3 grid(WW / (256 * COLS_PER_THR), BB, HH / ROWS_PER_BLOCK);
    pack_all_kernel<<<grid, 256>>>(x, xi, N, sep, out, out + XN, write_xi);
}